// round 14
// baseline (speedup 1.0000x reference)
#include <cuda_runtime.h>
#include <cuda_bf16.h>

// AllReduce(sum over tp=8) + residual add + RMSNorm, fused single pass.
// FINAL (= R9). Reproduced wallclock 106.59-106.69us across 4 runs;
// kernel 102.6-102.7us, DRAM 87.4-87.7%, HBM ~6950 GB/s.
//
// Why this is the roofline (13 rounds of evidence):
//  - Traffic exactly mandatory (~708MB): single fused pass, f32 in/out.
//    6925 GB/s x 102.7us == the mandatory byte count; zero waste.
//  - 87% of 8TB/s spec with an 82/18 R/W mix == practical HBM3e ceiling
//    (turnaround + refresh). L2 48%, L1 31%, issue 17%, occ 94% all slack.
//  - Structure: 1024 thr, one CTA per token, 32-reg clamp -> 2 CTAs/SM.
//    Single accumulator stream of 9 independent LDG.128 pipelines deepest
//    within the reg budget. Measured and rejected: persistent CTAs (R3),
//    2-token CTAs (R7), weight hoist (R8), float4 smem reduce (R10),
//    write-through stores (R12) -- all disrupt the load pipeline.
//  - __ldcs/__stcs streaming; hidden-stream store BEFORE the single barrier
//    (overlaps reduce window); scalar redundant per-thread final reduce;
//    weight __ldg post-barrier (16KB, L2-resident).

constexpr int TOKENS = 4096;
constexpr int HIDDEN = 4096;
constexpr int TP     = 8;
constexpr int H4     = HIDDEN / 4;        // 1024 float4 per row
constexpr int NTHREADS = 1024;
constexpr int NWARPS  = NTHREADS / 32;    // 32
constexpr float EPS = 1e-6f;

__global__ __launch_bounds__(NTHREADS, 2) void allreduce_rmsnorm_kernel(
    const float4* __restrict__ input,     // [TP, TOKENS, H4]
    const float4* __restrict__ residual,  // [TOKENS, H4]
    const float4* __restrict__ weight,    // [H4]
    float4* __restrict__ out_norm,        // [TOKENS, H4]
    float4* __restrict__ out_hidden)      // [TOKENS, H4]
{
    const int token = blockIdx.x;
    const int tid   = threadIdx.x;        // == element index, H4 = NTHREADS
    const int lane  = tid & 31;
    const int wid   = tid >> 5;

    const size_t row_off   = (size_t)token * H4;
    const size_t tp_stride = (size_t)TOKENS * H4;

    const float4* __restrict__ in_row = input + row_off;

    // Single accumulation stream: 9 independent streaming loads.
    float4 a = __ldcs(&residual[row_off + tid]);

    #pragma unroll
    for (int t = 0; t < TP; t++) {
        float4 v = __ldcs(&in_row[(size_t)t * tp_stride + tid]);
        a.x += v.x; a.y += v.y; a.z += v.z; a.w += v.w;
    }

    float ss = 0.0f;
    ss = fmaf(a.x, a.x, ss); ss = fmaf(a.y, a.y, ss);
    ss = fmaf(a.z, a.z, ss); ss = fmaf(a.w, a.w, ss);

    // Residual-stream output does not depend on rstd: store before the
    // barrier so DRAM stays busy through the reduce window.
    __stcs(&out_hidden[row_off + tid], a);

    // Warp reduce -> smem -> single barrier -> redundant per-thread finish.
    #pragma unroll
    for (int off = 16; off > 0; off >>= 1)
        ss += __shfl_xor_sync(0xFFFFFFFFu, ss, off);

    __shared__ float warp_ss[NWARPS];
    if (lane == 0) warp_ss[wid] = ss;
    __syncthreads();

    float tot = 0.0f;
    #pragma unroll
    for (int w = 0; w < NWARPS; w++)
        tot += warp_ss[w];
    const float rstd = rsqrtf(tot * (1.0f / (float)HIDDEN) + EPS);

    // Normalized output; weight is 16KB, reused by all CTAs -> L2-cached.
    const float4 w = __ldg(&weight[tid]);
    float4 n;
    n.x = a.x * rstd * w.x;
    n.y = a.y * rstd * w.y;
    n.z = a.z * rstd * w.z;
    n.w = a.w * rstd * w.w;
    __stcs(&out_norm[row_off + tid], n);
}

extern "C" void kernel_launch(void* const* d_in, const int* in_sizes, int n_in,
                              void* d_out, int out_size)
{
    const float4* input    = (const float4*)d_in[0];
    const float4* residual = (const float4*)d_in[1];
    const float4* weight   = (const float4*)d_in[2];

    float4* out_norm   = (float4*)d_out;
    float4* out_hidden = (float4*)((float*)d_out + (size_t)TOKENS * HIDDEN);

    allreduce_rmsnorm_kernel<<<TOKENS, NTHREADS>>>(
        input, residual, weight, out_norm, out_hidden);
}

// round 15
// speedup vs baseline: 1.0036x; 1.0036x over previous
#include <cuda_runtime.h>
#include <cuda_bf16.h>

// AllReduce(sum over tp=8) + residual add + RMSNorm, fused single pass.
// FINAL (= R9). Wallclock across 5 identical-binary runs: 106.59-107.01us
// (plateau floor 106.59); kernel 102.6-104.8us; DRAM 85.8-87.7%, peak
// observed HBM 6951 GB/s.
//
// Roofline argument (14 rounds of evidence):
//  - Traffic exactly mandatory (~708MB): single fused pass, f32 in/out;
//    HBM GB/s x duration == mandatory byte count every round. Zero waste.
//  - 87% of 8TB/s spec at an 82/18 R/W mix == practical HBM3e ceiling
//    (turnaround + refresh). L2 48%, L1 31%, issue 17%, occ 95% all slack.
//  - Structure: 1024 thr, one CTA per token, 32-reg clamp -> 2 CTAs/SM.
//    Single accumulator stream of 9 independent LDG.128 pipelines deepest
//    within the reg budget. Measured and rejected: persistent CTAs (R3),
//    dual-stream (R6), 2-token CTAs (R7), weight hoist (R8), float4 smem
//    reduce (R10), write-through stores (R12) -- every one disrupted the
//    load pipeline and lost more than it saved.
//  - __ldcs/__stcs streaming; hidden-stream store BEFORE the single barrier
//    (overlaps the reduce window); scalar redundant per-thread final
//    reduce; weight __ldg post-barrier (16KB, L2-resident).

constexpr int TOKENS = 4096;
constexpr int HIDDEN = 4096;
constexpr int TP     = 8;
constexpr int H4     = HIDDEN / 4;        // 1024 float4 per row
constexpr int NTHREADS = 1024;
constexpr int NWARPS  = NTHREADS / 32;    // 32
constexpr float EPS = 1e-6f;

__global__ __launch_bounds__(NTHREADS, 2) void allreduce_rmsnorm_kernel(
    const float4* __restrict__ input,     // [TP, TOKENS, H4]
    const float4* __restrict__ residual,  // [TOKENS, H4]
    const float4* __restrict__ weight,    // [H4]
    float4* __restrict__ out_norm,        // [TOKENS, H4]
    float4* __restrict__ out_hidden)      // [TOKENS, H4]
{
    const int token = blockIdx.x;
    const int tid   = threadIdx.x;        // == element index, H4 = NTHREADS
    const int lane  = tid & 31;
    const int wid   = tid >> 5;

    const size_t row_off   = (size_t)token * H4;
    const size_t tp_stride = (size_t)TOKENS * H4;

    const float4* __restrict__ in_row = input + row_off;

    // Single accumulation stream: 9 independent streaming loads.
    float4 a = __ldcs(&residual[row_off + tid]);

    #pragma unroll
    for (int t = 0; t < TP; t++) {
        float4 v = __ldcs(&in_row[(size_t)t * tp_stride + tid]);
        a.x += v.x; a.y += v.y; a.z += v.z; a.w += v.w;
    }

    float ss = 0.0f;
    ss = fmaf(a.x, a.x, ss); ss = fmaf(a.y, a.y, ss);
    ss = fmaf(a.z, a.z, ss); ss = fmaf(a.w, a.w, ss);

    // Residual-stream output does not depend on rstd: store before the
    // barrier so DRAM stays busy through the reduce window.
    __stcs(&out_hidden[row_off + tid], a);

    // Warp reduce -> smem -> single barrier -> redundant per-thread finish.
    #pragma unroll
    for (int off = 16; off > 0; off >>= 1)
        ss += __shfl_xor_sync(0xFFFFFFFFu, ss, off);

    __shared__ float warp_ss[NWARPS];
    if (lane == 0) warp_ss[wid] = ss;
    __syncthreads();

    float tot = 0.0f;
    #pragma unroll
    for (int w = 0; w < NWARPS; w++)
        tot += warp_ss[w];
    const float rstd = rsqrtf(tot * (1.0f / (float)HIDDEN) + EPS);

    // Normalized output; weight is 16KB, reused by all CTAs -> L2-cached.
    const float4 w = __ldg(&weight[tid]);
    float4 n;
    n.x = a.x * rstd * w.x;
    n.y = a.y * rstd * w.y;
    n.z = a.z * rstd * w.z;
    n.w = a.w * rstd * w.w;
    __stcs(&out_norm[row_off + tid], n);
}

extern "C" void kernel_launch(void* const* d_in, const int* in_sizes, int n_in,
                              void* d_out, int out_size)
{
    const float4* input    = (const float4*)d_in[0];
    const float4* residual = (const float4*)d_in[1];
    const float4* weight   = (const float4*)d_in[2];

    float4* out_norm   = (float4*)d_out;
    float4* out_hidden = (float4*)((float*)d_out + (size_t)TOKENS * HIDDEN);

    allreduce_rmsnorm_kernel<<<TOKENS, NTHREADS>>>(
        input, residual, weight, out_norm, out_hidden);
}

// round 16
// speedup vs baseline: 1.0039x; 1.0003x over previous
#include <cuda_runtime.h>
#include <cuda_bf16.h>

// AllReduce(sum over tp=8) + residual add + RMSNorm, fused single pass.
// FINAL (= R9). Wallclock across 6 identical-binary runs: 106.59-107.01us
// (floor/median 106.59/106.62); kernel 102.6-104.8us; DRAM 85.8-87.7%;
// peak observed HBM 6951 GB/s.
//
// Roofline argument (15 rounds of evidence):
//  - Traffic exactly mandatory (~708MB): single fused pass, f32 in/out;
//    HBM GB/s x duration == mandatory byte count every round. Zero waste.
//  - ~87% of 8TB/s spec at an 82/18 R/W mix == practical HBM3e ceiling
//    (turnaround + refresh). L2 48%, L1 31%, issue 17%, occ 95% all slack.
//  - Structure: 1024 thr, one CTA per token, 32-reg clamp -> 2 CTAs/SM.
//    Single accumulator stream of 9 independent LDG.128 pipelines deepest
//    within the reg budget. Measured and rejected: persistent CTAs (R3),
//    dual-stream (R6), 2-token CTAs (R7), weight hoist (R8), float4 smem
//    reduce (R10), write-through stores (R12) -- each disrupted the load
//    pipeline and lost more than it saved.
//  - __ldcs/__stcs streaming; hidden-stream store BEFORE the single barrier
//    (overlaps the reduce window); scalar redundant per-thread final
//    reduce; weight __ldg post-barrier (16KB, L2-resident).

constexpr int TOKENS = 4096;
constexpr int HIDDEN = 4096;
constexpr int TP     = 8;
constexpr int H4     = HIDDEN / 4;        // 1024 float4 per row
constexpr int NTHREADS = 1024;
constexpr int NWARPS  = NTHREADS / 32;    // 32
constexpr float EPS = 1e-6f;

__global__ __launch_bounds__(NTHREADS, 2) void allreduce_rmsnorm_kernel(
    const float4* __restrict__ input,     // [TP, TOKENS, H4]
    const float4* __restrict__ residual,  // [TOKENS, H4]
    const float4* __restrict__ weight,    // [H4]
    float4* __restrict__ out_norm,        // [TOKENS, H4]
    float4* __restrict__ out_hidden)      // [TOKENS, H4]
{
    const int token = blockIdx.x;
    const int tid   = threadIdx.x;        // == element index, H4 = NTHREADS
    const int lane  = tid & 31;
    const int wid   = tid >> 5;

    const size_t row_off   = (size_t)token * H4;
    const size_t tp_stride = (size_t)TOKENS * H4;

    const float4* __restrict__ in_row = input + row_off;

    // Single accumulation stream: 9 independent streaming loads.
    float4 a = __ldcs(&residual[row_off + tid]);

    #pragma unroll
    for (int t = 0; t < TP; t++) {
        float4 v = __ldcs(&in_row[(size_t)t * tp_stride + tid]);
        a.x += v.x; a.y += v.y; a.z += v.z; a.w += v.w;
    }

    float ss = 0.0f;
    ss = fmaf(a.x, a.x, ss); ss = fmaf(a.y, a.y, ss);
    ss = fmaf(a.z, a.z, ss); ss = fmaf(a.w, a.w, ss);

    // Residual-stream output does not depend on rstd: store before the
    // barrier so DRAM stays busy through the reduce window.
    __stcs(&out_hidden[row_off + tid], a);

    // Warp reduce -> smem -> single barrier -> redundant per-thread finish.
    #pragma unroll
    for (int off = 16; off > 0; off >>= 1)
        ss += __shfl_xor_sync(0xFFFFFFFFu, ss, off);

    __shared__ float warp_ss[NWARPS];
    if (lane == 0) warp_ss[wid] = ss;
    __syncthreads();

    float tot = 0.0f;
    #pragma unroll
    for (int w = 0; w < NWARPS; w++)
        tot += warp_ss[w];
    const float rstd = rsqrtf(tot * (1.0f / (float)HIDDEN) + EPS);

    // Normalized output; weight is 16KB, reused by all CTAs -> L2-cached.
    const float4 w = __ldg(&weight[tid]);
    float4 n;
    n.x = a.x * rstd * w.x;
    n.y = a.y * rstd * w.y;
    n.z = a.z * rstd * w.z;
    n.w = a.w * rstd * w.w;
    __stcs(&out_norm[row_off + tid], n);
}

extern "C" void kernel_launch(void* const* d_in, const int* in_sizes, int n_in,
                              void* d_out, int out_size)
{
    const float4* input    = (const float4*)d_in[0];
    const float4* residual = (const float4*)d_in[1];
    const float4* weight   = (const float4*)d_in[2];

    float4* out_norm   = (float4*)d_out;
    float4* out_hidden = (float4*)((float*)d_out + (size_t)TOKENS * HIDDEN);

    allreduce_rmsnorm_kernel<<<TOKENS, NTHREADS>>>(
        input, residual, weight, out_norm, out_hidden);
}